// round 1
// baseline (speedup 1.0000x reference)
#include <cuda_runtime.h>

// LatentLinearModel: r[i] = dot(U[users[i]], V[jokes[i]]) + a[users[i]] + b[jokes[i]] + g
// B = 1048576 rows, K = 64.
// Layout: 16 threads cooperate on one row; each thread loads one float4 (16B)
// of U-row and V-row => the 256B row is covered by exactly 2x128B cache lines,
// fully coalesced. 4-step shfl_xor reduction within the 16-lane group.

#define TPR 16          // threads per row
#define BLOCK 256       // 16 rows per block

__global__ void latent_linear_kernel(const int* __restrict__ users,
                                     const int* __restrict__ jokes,
                                     const float4* __restrict__ U4,
                                     const float4* __restrict__ V4,
                                     const float* __restrict__ a,
                                     const float* __restrict__ b,
                                     const float* __restrict__ g,
                                     float* __restrict__ out,
                                     int B) {
    int tid = blockIdx.x * blockDim.x + threadIdx.x;
    int row = tid >> 4;          // tid / 16
    int lane = tid & (TPR - 1);  // tid % 16
    if (row >= B) return;

    int u = __ldg(&users[row]);
    int j = __ldg(&jokes[row]);

    // Each row of U/V is 64 floats = 16 float4s.
    float4 uu = __ldg(&U4[(size_t)u * 16 + lane]);
    float4 vv = __ldg(&V4[(size_t)j * 16 + lane]);

    float d = uu.x * vv.x + uu.y * vv.y + uu.z * vv.z + uu.w * vv.w;

    // Reduce across the 16-lane group (lanes of a half... quarter-warp group).
    d += __shfl_xor_sync(0xffffffffu, d, 8);
    d += __shfl_xor_sync(0xffffffffu, d, 4);
    d += __shfl_xor_sync(0xffffffffu, d, 2);
    d += __shfl_xor_sync(0xffffffffu, d, 1);

    if (lane == 0) {
        out[row] = d + __ldg(&a[u]) + __ldg(&b[j]) + __ldg(&g[0]);
    }
}

extern "C" void kernel_launch(void* const* d_in, const int* in_sizes, int n_in,
                              void* d_out, int out_size) {
    // metadata order: users, jokes, U, V, a, b, g
    const int*    users = (const int*)d_in[0];
    const int*    jokes = (const int*)d_in[1];
    const float4* U4    = (const float4*)d_in[2];
    const float4* V4    = (const float4*)d_in[3];
    const float*  a     = (const float*)d_in[4];
    const float*  b     = (const float*)d_in[5];
    const float*  g     = (const float*)d_in[6];
    float* out = (float*)d_out;

    int B = in_sizes[0];  // number of rows (users index count)

    int rows_per_block = BLOCK / TPR;  // 16
    int grid = (B + rows_per_block - 1) / rows_per_block;
    latent_linear_kernel<<<grid, BLOCK>>>(users, jokes, U4, V4, a, b, g, out, B);
}

// round 2
// speedup vs baseline: 1.4850x; 1.4850x over previous
#include <cuda_runtime.h>

// LatentLinearModel: r[i] = dot(U[users[i]], V[jokes[i]]) + a[users[i]] + b[jokes[i]] + g
// B = 1048576 rows, K = 64.
//
// Round 2: latency-bound fix. Each 16-lane group now handles ROWS_PER_GROUP=4
// rows. All 8 gather float4 loads (4 U-rows + 4 V-rows, 16B per lane each) are
// issued back-to-back before any use -> MLP per thread goes 2 -> 8, which is
// what the B300 LDG queue needs to hide the ~600cyc DRAM latency.

#define TPR   16        // threads per row
#define RPG   4         // rows per 16-lane group
#define BLOCK 256       // 16 groups per block -> 64 rows per block

__global__ void __launch_bounds__(BLOCK)
latent_linear_kernel(const int* __restrict__ users,
                     const int* __restrict__ jokes,
                     const float4* __restrict__ U4,
                     const float4* __restrict__ V4,
                     const float* __restrict__ a,
                     const float* __restrict__ b,
                     const float* __restrict__ g,
                     float* __restrict__ out,
                     int B) {
    int lane = threadIdx.x & (TPR - 1);
    int gid  = (blockIdx.x * BLOCK + threadIdx.x) >> 4;   // group id
    int row0 = gid * RPG;
    if (row0 >= B) return;

    // ---- Phase 1: index loads (coalesced/broadcast) ----
    int us[RPG], js[RPG];
#pragma unroll
    for (int r = 0; r < RPG; r++) {
        int row = row0 + r;
        us[r] = __ldg(&users[row]);
        js[r] = __ldg(&jokes[row]);
    }

    // ---- Phase 2: issue ALL gathers before any use (MLP = 8 per thread) ----
    float4 uu[RPG], vv[RPG];
#pragma unroll
    for (int r = 0; r < RPG; r++) {
        uu[r] = __ldg(&U4[(size_t)us[r] * 16 + lane]);
        vv[r] = __ldg(&V4[(size_t)js[r] * 16 + lane]);
    }

    // Bias loads in flight concurrently with the gathers (lane 0 only needs them).
    float bias[RPG];
    if (lane == 0) {
#pragma unroll
        for (int r = 0; r < RPG; r++) {
            bias[r] = __ldg(&a[us[r]]) + __ldg(&b[js[r]]);
        }
    }
    float gg = __ldg(&g[0]);

    // ---- Phase 3: dot + 16-lane reduction per row ----
#pragma unroll
    for (int r = 0; r < RPG; r++) {
        float d = uu[r].x * vv[r].x + uu[r].y * vv[r].y
                + uu[r].z * vv[r].z + uu[r].w * vv[r].w;
        d += __shfl_xor_sync(0xffffffffu, d, 8);
        d += __shfl_xor_sync(0xffffffffu, d, 4);
        d += __shfl_xor_sync(0xffffffffu, d, 2);
        d += __shfl_xor_sync(0xffffffffu, d, 1);
        if (lane == 0) {
            out[row0 + r] = d + bias[r] + gg;
        }
    }
}

extern "C" void kernel_launch(void* const* d_in, const int* in_sizes, int n_in,
                              void* d_out, int out_size) {
    // metadata order: users, jokes, U, V, a, b, g
    const int*    users = (const int*)d_in[0];
    const int*    jokes = (const int*)d_in[1];
    const float4* U4    = (const float4*)d_in[2];
    const float4* V4    = (const float4*)d_in[3];
    const float*  a     = (const float*)d_in[4];
    const float*  b     = (const float*)d_in[5];
    const float*  g     = (const float*)d_in[6];
    float* out = (float*)d_out;

    int B = in_sizes[0];

    int rows_per_block = (BLOCK / TPR) * RPG;   // 64
    int grid = (B + rows_per_block - 1) / rows_per_block;
    latent_linear_kernel<<<grid, BLOCK>>>(users, jokes, U4, V4, a, b, g, out, B);
}